// round 4
// baseline (speedup 1.0000x reference)
#include <cuda_runtime.h>
#include <cstdint>

// ifft(fft(x)) == x (identity). Confirmed in R3: output is n float32 (real
// part). Pure HBM-bound 256MB -> 256MB streaming copy.
//
// Tuning vs R3 winner (78.2us kernel, DRAM 75.6%):
//  - 4 front-batched LDG.128 per thread (MLP 2 -> 4)
//  - __ldcs / __stcs streaming hints (touch-once data, don't pollute L2)
//  - each block moves 16KB contiguously: 4 coalesced 4KB chunks

__global__ __launch_bounds__(256) void copy4_kernel(
    const float4* __restrict__ in, float4* __restrict__ out, long long n_vec4)
{
    // Block b owns float4 range [b*1024, b*1024+1024).
    long long base = (long long)blockIdx.x * 1024 + threadIdx.x;

    long long i0 = base;
    long long i1 = base + 256;
    long long i2 = base + 512;
    long long i3 = base + 768;

    if (i3 < n_vec4) {
        // Fast path: all four in-bounds. Front-batch the loads (MLP=4).
        float4 a0 = __ldcs(in + i0);
        float4 a1 = __ldcs(in + i1);
        float4 a2 = __ldcs(in + i2);
        float4 a3 = __ldcs(in + i3);
        __stcs(out + i0, a0);
        __stcs(out + i1, a1);
        __stcs(out + i2, a2);
        __stcs(out + i3, a3);
    } else {
        if (i0 < n_vec4) __stcs(out + i0, __ldcs(in + i0));
        if (i1 < n_vec4) __stcs(out + i1, __ldcs(in + i1));
        if (i2 < n_vec4) __stcs(out + i2, __ldcs(in + i2));
    }
}

// ---- Case B: expand n floats -> 2n floats (re, 0, re, 0, ...) ----------
// Kept as a guard in case out_size layout ever differs; not expected to fire.
__global__ __launch_bounds__(256) void expand_kernel(
    const float4* __restrict__ in, float4* __restrict__ out, long long n_vec4)
{
    long long i = (long long)blockIdx.x * blockDim.x + threadIdx.x;
    if (i >= n_vec4) return;
    float4 a = __ldcs(in + i);
    long long o = i * 2;
    __stcs(out + o,     make_float4(a.x, 0.0f, a.y, 0.0f));
    __stcs(out + o + 1, make_float4(a.z, 0.0f, a.w, 0.0f));
}

// ---- Fallback: scalar, handles any size/alignment ----------------------
__global__ void scalar_kernel(const float* __restrict__ in,
                              float* __restrict__ out,
                              long long n_in, long long n_out)
{
    long long i = (long long)blockIdx.x * blockDim.x + threadIdx.x;
    long long stride = (long long)gridDim.x * blockDim.x;
    if (n_out == n_in) {
        for (long long j = i; j < n_out; j += stride) out[j] = in[j];
    } else {
        for (long long j = i; j < n_out; j += stride)
            out[j] = (j & 1) ? 0.0f : in[j >> 1];
    }
}

extern "C" void kernel_launch(void* const* d_in, const int* in_sizes, int n_in,
                              void* d_out, int out_size) {
    const float* x = (const float*)d_in[0];
    long long n = (long long)in_sizes[0];
    long long nout = (long long)out_size;

    bool aligned = ((uintptr_t)x % 16 == 0) && ((uintptr_t)d_out % 16 == 0);

    if (nout == n && aligned && (n % 4 == 0)) {
        long long n_vec4 = n / 4;                  // 16,777,216 for this shape
        long long grid = (n_vec4 + 1023) / 1024;   // 1024 float4 per block
        copy4_kernel<<<(unsigned)grid, 256>>>(
            (const float4*)x, (float4*)d_out, n_vec4);
    } else if (nout == 2 * n && aligned && (n % 4 == 0)) {
        long long n_vec4 = n / 4;
        long long grid = (n_vec4 + 255) / 256;
        expand_kernel<<<(unsigned)grid, 256>>>(
            (const float4*)x, (float4*)d_out, n_vec4);
    } else {
        long long grid = (nout + 255) / 256;
        if (grid > 2147483647LL) grid = 2147483647LL;
        scalar_kernel<<<(unsigned)grid, 256>>>(x, (float*)d_out, n, nout);
    }
}